// round 4
// baseline (speedup 1.0000x reference)
#include <cuda_runtime.h>

// uDTW forward DP. B=32, N=M=512, alpha=1, BIG=1e30.
// 1 CTA/batch, 128 threads = 4 warps, 4 consecutive rows per thread.
// Barrier-free: warps run skewed; inter-warp boundary (last row of warp w-1)
// passes through a per-diagonal smem history with release/acquire 64-bit
// packed {R,D} and sentinel spin (R >= 0 always; sentinel = -1).
// S (SigR) never feeds the recurrence -> only thread 127 tracks it.

#define BIGV 1e30f
#define NN   512
#define BB   32
#define RPT  4
#define WARPS 4

__device__ __forceinline__ void bpub(unsigned addr, float r, float dv) {
    unsigned long long p =
        ((unsigned long long)__float_as_uint(dv) << 32) | (unsigned long long)__float_as_uint(r);
    asm volatile("st.release.cta.shared.b64 [%0], %1;" :: "r"(addr), "l"(p) : "memory");
}
__device__ __forceinline__ void bget(unsigned addr, float& r, float& dv) {
    unsigned long long p;
    float rv;
    while (true) {
        asm volatile("ld.acquire.cta.shared.b64 %0, [%1];" : "=l"(p) : "r"(addr) : "memory");
        rv = __uint_as_float((unsigned)(p & 0xffffffffull));
        if (rv >= 0.f) break;
    }
    r = rv;
    dv = __uint_as_float((unsigned)(p >> 32));
}
__device__ __forceinline__ void l2pf(const float* p) {
    asm volatile("prefetch.global.L2 [%0];" :: "l"(p));
}

__global__ __launch_bounds__(128, 1)
void softdtw_k3(const float* __restrict__ D, const float* __restrict__ Sig,
                float* __restrict__ out) {
    __shared__ unsigned long long sB[WARPS - 1][2 * NN + 1];  // [producer warp][diag]

    const int b    = blockIdx.x;
    const int t    = threadIdx.x;
    const int lane = t & 31;
    const int w    = t >> 5;
    const int r0   = 128 * w + RPT * lane + 1;   // first row (1-indexed)
    const bool lastT = (t == 127);

    // init boundary buffers to sentinel (R part = -1)
    const unsigned long long sent = (unsigned long long)__float_as_uint(-1.0f);
    for (int idx = t; idx < (WARPS - 1) * (2 * NN + 1); idx += 128)
        ((unsigned long long*)sB)[idx] = sent;
    __syncthreads();   // only barrier in the kernel

    unsigned sb_pub = 0, sb_get = 0;
    if (w < WARPS - 1) sb_pub = (unsigned)__cvta_generic_to_shared(&sB[w][0]);
    if (w > 0)         sb_get = (unsigned)__cvta_generic_to_shared(&sB[w - 1][0]);

    const float* pDrow = D + (size_t)b * NN * NN + (size_t)(r0 - 1) * NN;
    const float* pG2   = Sig + (size_t)b * NN * NN + (size_t)510 * NN;  // row 511
    const float* pG3   = pG2 + NN;                                      // row 512

    // per-row DP state (diag d-1 / d-2)
    float R1[RPT], R2[RPT], D1[RPT], D2[RPT];
#pragma unroll
    for (int k = 0; k < RPT; ++k) { R1[k] = BIGV; R2[k] = BIGV; D1[k] = 0.f; D2[k] = 0.f; }
    float pR2 = (t == 0) ? 0.f : BIGV, pD2 = 0.f;   // boundary row at diag d-2

    // depth-2 prefetch of D diag values: dc = step d, dn = step d+1
    float dc[RPT], dn[RPT];
#pragma unroll
    for (int k = 0; k < RPT; ++k) {
        int c2 = 1 - (r0 + k);
        dc[k] = ((unsigned)c2 < NN) ? pDrow[k * NN + c2] : 0.f;
        int c3 = 2 - (r0 + k);
        dn[k] = ((unsigned)c3 < NN) ? pDrow[k * NN + c3] : 0.f;
    }
    float gc2 = 0.f, gn2 = 0.f, gc3 = 0.f, gn3 = 0.f;   // Sig prefetch (t==127)
    float G1r2 = 0.f, G2r2 = 0.f, G1r3 = 0.f;
    float lastS = BIGV;

    const int wlo = 128 * w + 2;          // first diag any row of this warp is active
    const int whi = 128 * w + 128 + NN;   // last diag
    const int rb  = 128 * w;              // boundary row feeding this warp (w>0)
    const int rw  = 128 * w + 128;        // boundary row this warp publishes

#pragma unroll 2
    for (int d = 2; d <= 2 * NN; ++d) {
        if (d >= wlo && d <= whi) {       // warp-uniform
            // neighbor-row (row r0-1) values at diag d-1
            float pR1 = __shfl_up_sync(0xffffffffu, R1[RPT - 1], 1);
            float pD1 = __shfl_up_sync(0xffffffffu, D1[RPT - 1], 1);
            if (lane == 0) {
                if (w == 0) { pR1 = BIGV; pD1 = 0.f; }
                else if ((d - 1 >= rb + 1) && (d - 1 <= rb + NN))
                    bget(sb_get + (unsigned)(d - 1) * 8u, pR1, pD1);
                else { pR1 = BIGV; pD1 = 0.f; }
            }

            float nR[RPT], e0s = 0.f, e1s = 0.f, e2s = 0.f, invs = 0.f;
#pragma unroll
            for (int k = 0; k < RPT; ++k) {
                float Pr2 = (k == 0) ? pR2 : R2[k - 1];
                float Pr1 = (k == 0) ? pR1 : R1[k - 1];
                float Pd2 = (k == 0) ? pD2 : D2[k - 1];
                float Pd1 = (k == 0) ? pD1 : D1[k - 1];
                float m  = fminf(fminf(Pr2, Pr1), R1[k]);
                float e0 = __expf(m - Pr2);
                float e1 = __expf(m - Pr1);
                float e2 = __expf(m - R1[k]);
                float iv = __fdividef(1.f, e0 + e1 + e2);
                nR[k] = fmaf(iv, fmaf(e2, D1[k], fmaf(e1, Pd1, e0 * Pd2)), dc[k]);
                if (k == RPT - 1) { e0s = e0; e1s = e1; e2s = e2; invs = iv; }
            }
            if (lastT) {   // SigR for row 512, same weights as cell k=3
                float nS = fmaf(invs, fmaf(e2s, G1r3, fmaf(e1s, G1r2, e0s * G2r2)), gc3);
                if (d >= 513) lastS = nS;
                G2r2 = G1r2; G1r2 = gc2; G1r3 = gc3;
            }
            // rotate state
#pragma unroll
            for (int k = 0; k < RPT; ++k) {
                bool vk = (d >= r0 + k + 1) && (d <= r0 + k + NN);
                R2[k] = R1[k]; R1[k] = vk ? nR[k] : BIGV;
                D2[k] = D1[k]; D1[k] = dc[k];
            }
            pR2 = pR1; pD2 = pD1;

            // publish boundary (post-rotation = this diag's values of last row)
            if (lane == 31 && w < WARPS - 1 && d >= rw + 1 && d <= rw + NN)
                bpub(sb_pub + (unsigned)d * 8u, R1[RPT - 1], D1[RPT - 1]);
        }

        // advance prefetch (loads for step d+2), always executed
#pragma unroll
        for (int k = 0; k < RPT; ++k) {
            dc[k] = dn[k];
            int c = d + 1 - (r0 + k);
            dn[k] = ((unsigned)c < NN) ? pDrow[k * NN + c] : 0.f;
            if ((unsigned)(c + 16) < NN) l2pf(pDrow + k * NN + c + 16);
        }
        if (lastT) {
            gc2 = gn2; gc3 = gn3;
            int c2 = d + 1 - 511, c3 = d + 1 - 512;
            gn2 = ((unsigned)c2 < NN) ? pG2[c2] : 0.f;
            gn3 = ((unsigned)c3 < NN) ? pG3[c3] : 0.f;
        }
    }

    if (lastT) {
        out[b]      = R1[RPT - 1];   // R[b, N, M]
        out[BB + b] = lastS;         // SigR[b, N, M]
    }
}

extern "C" void kernel_launch(void* const* d_in, const int* in_sizes, int n_in,
                              void* d_out, int out_size) {
    const float* D   = (const float*)d_in[0];
    const float* Sig = (const float*)d_in[1];
    float* out = (float*)d_out;
    softdtw_k3<<<BB, 128>>>(D, Sig, out);
}

// round 5
// speedup vs baseline: 5.1558x; 5.1558x over previous
#include <cuda_runtime.h>

// uDTW forward DP. B=32, N=M=512, alpha=1, BIG=1e30.
// 1 CTA/batch, 256 threads = 8 warps, 2 rows/thread.
// State is E = exp(-R) (valid since R in [0,2); invalid cells -> E=0),
// so each cell needs only 1 EX2 + 1 RCP.
// K=4 diagonals per __syncthreads with warps skewed by 4 diags each;
// inter-warp boundary {E,D} passes through a 16-slot smem ring per boundary.
// SigR never feeds the recurrence -> only thread 255 tracks it.

#define BIGV 1e30f
#define NN   512
#define BB   32
#define KS   4
#define WPS  8
#define RING 16
#define PMAX 263   // warp 7 reaches diag 1024 at p=262

__global__ __launch_bounds__(256, 1)
void softdtw_k5(const float* __restrict__ D, const float* __restrict__ Sig,
                float* __restrict__ out) {
    __shared__ float2 ring[WPS - 1][RING];   // [producer warp][diag & 15] = {E, D}

    const int b    = blockIdx.x;
    const int t    = threadIdx.x;
    const int lane = t & 31;
    const int w    = t >> 5;
    const int r0   = 64 * w + 2 * lane + 1;  // rows r0, r0+1 (1-indexed)
    const bool lastT = (t == 255);

    if (t < (WPS - 1) * RING) ((float2*)ring)[t] = make_float2(0.f, 0.f);

    const float* rowA = D + (size_t)b * NN * NN + (size_t)(r0 - 1) * NN;
    const float* rowB = rowA + NN;
    const float* gA   = Sig + (size_t)b * NN * NN + (size_t)510 * NN; // row 511
    const float* gB   = gA + NN;                                     // row 512

    // E/D state at diag d-1 (1) and d-2 (2); rows a (r0) and b (r0+1).
    float E1a = 0.f, E2a = 0.f, D1a = 0.f, D2a = 0.f;
    float E1b = 0.f, D1b = 0.f;
    float pE1 = 0.f, pE2 = 0.f, pD1 = 0.f, pD2 = 0.f;   // row r0-1 preds
    float G1a = 0.f, G2a = 0.f, G1b = 0.f;              // Sig state (t==255)
    float lastR = BIGV, lastS = BIGV;

    const int wlo = 64 * w + 2;        // warp active diag window
    const int whi = 64 * w + 64 + NN;
    const int rb  = 64 * w;            // boundary row feeding this warp (w>0)

    // prefetch for period 0 (cols are guarded -> 0 outside [0,NN))
    float dcA[KS], dcB[KS], dnA[KS], dnB[KS];
    float gcA[KS] = {0,0,0,0}, gcB[KS] = {0,0,0,0};
    float gnA[KS] = {0,0,0,0}, gnB[KS] = {0,0,0,0};
    {
        int db0 = 2 - KS * w;
#pragma unroll
        for (int s = 0; s < KS; ++s) {
            int ca = db0 + s - r0 - 1, cb = ca - 1;
            dcA[s] = ((unsigned)ca < NN) ? rowA[ca] : 0.f;
            dcB[s] = ((unsigned)cb < NN) ? rowB[cb] : 0.f;
            if (lastT) {
                gcA[s] = ((unsigned)ca < NN) ? gA[ca] : 0.f;
                gcB[s] = ((unsigned)cb < NN) ? gB[cb] : 0.f;
            }
        }
    }
    __syncthreads();

    for (int p = 0; p < PMAX; ++p) {
        const int dbase = 2 + KS * (p - w);

        // issue loads for next period (consumed after the coming barrier)
        {
            int nb = dbase + KS;
#pragma unroll
            for (int s = 0; s < KS; ++s) {
                int ca = nb + s - r0 - 1, cb = ca - 1;
                dnA[s] = ((unsigned)ca < NN) ? rowA[ca] : 0.f;
                dnB[s] = ((unsigned)cb < NN) ? rowB[cb] : 0.f;
                if (lastT) {
                    gnA[s] = ((unsigned)ca < NN) ? gA[ca] : 0.f;
                    gnB[s] = ((unsigned)cb < NN) ? gB[cb] : 0.f;
                }
            }
        }

#pragma unroll
        for (int s = 0; s < KS; ++s) {
            const int d = dbase + s;
            if (d < wlo || d > whi) continue;          // warp-uniform

            // predecessor-row (r0-1) values at diag d-1 / d-2
            float sE1 = __shfl_up_sync(0xffffffffu, E1b, 1);
            float sD1 = __shfl_up_sync(0xffffffffu, D1b, 1);
            if (lane == 0) {
                if (w == 0) {
                    pE1 = 0.f; pD1 = 0.f;
                    pE2 = (d == 2) ? 1.f : 0.f; pD2 = 0.f;  // R[0][0]=0 at diag 0
                } else {
                    int j1 = d - 1 - rb - 1, j2 = d - 2 - rb - 1;
                    float2 v1r = ((unsigned)j1 < NN) ? ring[w-1][(d-1) & (RING-1)]
                                                     : make_float2(0.f, 0.f);
                    float2 v2r = ((unsigned)j2 < NN) ? ring[w-1][(d-2) & (RING-1)]
                                                     : make_float2(0.f, 0.f);
                    pE1 = v1r.x; pD1 = v1r.y; pE2 = v2r.x; pD2 = v2r.y;
                }
            } else { pE1 = sE1; pD1 = sD1; }

            // cell a (row r0): weights {pE2, pE1, E1a}, values {pD2, pD1, D1a}
            float suma = (pE2 + pE1) + E1a;
            float iva  = __fdividef(1.f, suma);
            float numa = fmaf(E1a, D1a, fmaf(pE1, pD1, pE2 * pD2));
            float nRa  = fmaf(numa, iva, dcA[s]);
            // cell b (row r0+1): weights {E2a, E1a, E1b}, values {D2a, D1a, D1b}
            float sumb = (E2a + E1a) + E1b;
            float ivb  = __fdividef(1.f, sumb);
            float numb = fmaf(E1b, D1b, fmaf(E1a, D1a, E2a * D2a));
            float nRb  = fmaf(numb, ivb, dcB[s]);

            const bool v0 = ((unsigned)(d - r0 - 1) < NN);
            const bool v1 = ((unsigned)(d - r0 - 2) < NN);
            float Ea = v0 ? __expf(-nRa) : 0.f;
            float Eb = v1 ? __expf(-nRb) : 0.f;

            if (lastT) {   // SigR of row 512: same weights as cell b
                float nSb = fmaf(fmaf(E1b, G1b, fmaf(E1a, G1a, E2a * G2a)),
                                 ivb, gcB[s]);
                if (v1) { lastS = nSb; lastR = nRb; }
                G2a = G1a; G1a = gcA[s]; G1b = gcB[s];
            }

            // rotate state to end of diag d
            pE2 = pE1; pD2 = pD1;
            E2a = E1a; D2a = D1a;
            E1a = Ea;  D1a = dcA[s];
            E1b = Eb;  D1b = dcB[s];

            if (lane == 31 && w < WPS - 1)
                ring[w][d & (RING-1)] = make_float2(E1b, D1b);
        }

#pragma unroll
        for (int s = 0; s < KS; ++s) {
            dcA[s] = dnA[s]; dcB[s] = dnB[s];
            gcA[s] = gnA[s]; gcB[s] = gnB[s];
        }
        __syncthreads();
    }

    if (lastT) {
        out[b]      = lastR;   // R[b, N, M]
        out[BB + b] = lastS;   // SigR[b, N, M]
    }
}

extern "C" void kernel_launch(void* const* d_in, const int* in_sizes, int n_in,
                              void* d_out, int out_size) {
    const float* D   = (const float*)d_in[0];
    const float* Sig = (const float*)d_in[1];
    float* out = (float*)d_out;
    softdtw_k5<<<BB, 256>>>(D, Sig, out);
}

// round 9
// speedup vs baseline: 7.4685x; 1.4486x over previous
#include <cuda_runtime.h>

// uDTW forward DP. B=32, N=M=512, alpha=1.
// 1 CTA/batch, 256 threads = 8 warps, 2 rows/thread (rows r0=64w+2*lane+1, r0+1).
// State E = exp(-R) (R in [0,2) for valid cells; invalid -> E = 0).
// K=8 diagonals per __syncthreads, warps skewed by 8 diags; inter-warp boundary
// E passes through a 32-slot smem ring (consumer w reads ring[w], producer
// writes ring[w+1]). Substep body is branch-free (SEL/predication only).
// Neighbor-row D values are streamed from gmem (3 row streams per thread).
// SigR computed once post-loop from the captured final-cell weights.

#define NN     512
#define BB     32
#define KS     8
#define WPS    8
#define RINGSZ 32
#define PMAX   135

__global__ __launch_bounds__(256, 1)
void softdtw_k6(const float* __restrict__ D, const float* __restrict__ Sig,
                float* __restrict__ out) {
    __shared__ float ring[WPS][RINGSZ];

    const int b    = blockIdx.x;
    const int t    = threadIdx.x;
    const int lane = t & 31;
    const int w    = t >> 5;
    const int r0   = 64 * w + 2 * lane + 1;   // matrix rows r0, r0+1 (1-indexed)
    const int rb   = 64 * w;                  // boundary row feeding this warp

    if (t < WPS * RINGSZ) ((float*)ring)[t] = 0.f;

    const size_t base = (size_t)b * NN * NN;
    const float* rowA = D + base + (size_t)(r0 - 1) * NN;  // row r0
    const float* rowB = rowA + NN;                          // row r0+1
    const float* rowP = rowA - NN;                          // row r0-1
    const bool haveP = (t > 0);
    const bool pubP  = (lane == 31) && (w < WPS - 1);

    // E-state (diag d-1 / d-2); cpE1 = neighbor-row E at previous diag
    float E1a = 0.f, E2a = 0.f, E1b = 0.f;
    float cpE1 = (t == 0) ? 1.f : 0.f;        // sentinel: E(R[0][0]=0) = 1
    float A1 = 0.f, A2 = 0.f, B1 = 0.f, P1 = 0.f;   // cross-period D carries
    float capE2a = 0.f, capE1a = 0.f, capE1b = 0.f, capR = 0.f;

    // buf[parity][0]=rowA vals, [1]=rowB vals, [2]=rowP vals; index s <-> diag dbase+s
    float buf[2][3][KS];
    int cb = 1 - 8 * w - r0;   // col (0-based) of rowA value for substep 0

#pragma unroll
    for (int s = 0; s < KS; s += 2) {           // A and P cols are even-aligned
        int c = cb + s;
        if ((unsigned)c < NN) { float2 v = *(const float2*)(rowA + c); buf[0][0][s] = v.x; buf[0][0][s+1] = v.y; }
        else                  { buf[0][0][s] = 0.f; buf[0][0][s+1] = 0.f; }
        if (haveP && (unsigned)c < NN) { float2 v = *(const float2*)(rowP + c); buf[0][2][s] = v.x; buf[0][2][s+1] = v.y; }
        else                  { buf[0][2][s] = 0.f; buf[0][2][s+1] = 0.f; }
    }
#pragma unroll
    for (int s = 0; s < KS; ++s) {
        int c = cb + s - 1;                     // rowB col (odd) -> scalar
        buf[0][1][s] = ((unsigned)c < NN) ? rowB[c] : 0.f;
    }
    __syncthreads();

    const int wlo = 64 * w + 2;
    const int whi = 64 * w + 576;

#pragma unroll 2
    for (int p = 0; p < PMAX; ++p) {
        const int cur = p & 1, nxt = cur ^ 1;
        const int dbase = 2 + KS * (p - w);

        // prefetch next period into buf[nxt]
#pragma unroll
        for (int s = 0; s < KS; s += 2) {
            int c = cb + KS + s;
            if ((unsigned)c < NN) { float2 v = *(const float2*)(rowA + c); buf[nxt][0][s] = v.x; buf[nxt][0][s+1] = v.y; }
            else                  { buf[nxt][0][s] = 0.f; buf[nxt][0][s+1] = 0.f; }
            if (haveP && (unsigned)c < NN) { float2 v = *(const float2*)(rowP + c); buf[nxt][2][s] = v.x; buf[nxt][2][s+1] = v.y; }
            else                  { buf[nxt][2][s] = 0.f; buf[nxt][2][s+1] = 0.f; }
        }
#pragma unroll
        for (int s = 0; s < KS; ++s) {
            int c = cb + KS + s - 1;
            buf[nxt][1][s] = ((unsigned)c < NN) ? rowB[c] : 0.f;
        }

        if (dbase <= whi && dbase + KS - 1 >= wlo) {   // whole-period activity check
#pragma unroll
            for (int s = 0; s < KS; ++s) {
                const int d    = dbase + s;
                const float dA  = buf[cur][0][s];                         // D(r0,   d)
                const float dB  = buf[cur][1][s];                         // D(r0+1, d)
                const float pD1 = buf[cur][2][s];                         // D(r0-1, d-1)
                const float pD2 = (s >= 1) ? buf[cur][2][s-1] : P1;       // D(r0-1, d-2)
                const float D1a = (s >= 1) ? buf[cur][0][s-1] : A1;       // D(r0,   d-1)
                const float D2a = (s >= 2) ? buf[cur][0][s-2] : ((s == 1) ? A1 : A2);
                const float D1b = (s >= 1) ? buf[cur][1][s-1] : B1;       // D(r0+1, d-1)

                // neighbor-row E at diag d-1: shfl for lanes>0, ring broadcast for lane 0
                float sE1 = __shfl_up_sync(0xffffffffu, E1b, 1);
                float rv  = ring[w][(d - 1) & (RINGSZ - 1)];
                int   jj  = d - 1 - rb;
                float bnd = ((unsigned)(jj - 1) < NN) ? rv : 0.f;
                float pE1 = (lane == 0) ? bnd : sE1;
                float pE2 = cpE1;

                // cell A (row r0): weights {pE2, pE1, E1a}
                float suma = (pE2 + pE1) + E1a;
                float iva  = __fdividef(1.f, suma);
                float numa = fmaf(E1a, D1a, fmaf(pE1, pD1, pE2 * pD2));
                float nRa  = fmaf(numa, iva, dA);
                // cell B (row r0+1): weights {E2a, E1a, E1b}
                float sumb = (E2a + E1a) + E1b;
                float ivb  = __fdividef(1.f, sumb);
                float numb = fmaf(E1b, D1b, fmaf(E1a, D1a, E2a * D2a));
                float nRb  = fmaf(numb, ivb, dB);

                bool v0 = ((unsigned)(d - r0 - 1) < NN);
                bool v1 = ((unsigned)(d - r0 - 2) < NN);
                float Ea = v0 ? __expf(-nRa) : 0.f;
                float Eb = v1 ? __expf(-nRb) : 0.f;

                if (d == 2 * NN) { capE2a = E2a; capE1a = E1a; capE1b = E1b; capR = nRb; }

                E2a = E1a; E1a = Ea; E1b = Eb; cpE1 = pE1;

                if (pubP) ring[w + 1][d & (RINGSZ - 1)] = Eb;   // predicated STS
            }
        }

        A2 = buf[cur][0][KS-2]; A1 = buf[cur][0][KS-1];
        B1 = buf[cur][1][KS-1]; P1 = buf[cur][2][KS-1];
        cb += KS;
        __syncthreads();
    }

    if (t == 255) {
        // final cell (512,512): weights {capE2a, capE1a, capE1b} over
        // Sig preds (511,511),(511,512),(512,511); base Sig(512,512).
        const float* Sg = Sig + base;
        float s00 = Sg[510 * NN + 510];
        float s01 = Sg[510 * NN + 511];
        float s10 = Sg[511 * NN + 510];
        float s11 = Sg[511 * NN + 511];
        float sum = (capE2a + capE1a) + capE1b;
        float lastS = s11 + fmaf(capE2a, s00, fmaf(capE1a, s01, capE1b * s10)) / sum;
        out[b]      = capR;    // R[b, N, M]
        out[BB + b] = lastS;   // SigR[b, N, M]
    }
}

extern "C" void kernel_launch(void* const* d_in, const int* in_sizes, int n_in,
                              void* d_out, int out_size) {
    const float* D   = (const float*)d_in[0];
    const float* Sig = (const float*)d_in[1];
    float* out = (float*)d_out;
    softdtw_k6<<<BB, 256>>>(D, Sig, out);
}

// round 13
// speedup vs baseline: 7.9815x; 1.0687x over previous
#include <cuda_runtime.h>

// uDTW forward DP. B=32, N=M=512, alpha=1.
// 1 CTA/batch, 512 threads = 16 warps, 1 row per thread (row r = t+1).
// State E = exp(-R) (R in [0,2) for valid cells; invalid -> E = 0).
// K=8 diagonals per __syncthreads, warps skewed by 8 diags; inter-warp
// boundary {E,D} via 32-slot float2 smem ring (warp w reads ring[w],
// lane31 of warp w writes ring[w+1]). Branch-free substep body.
// Final period peeled (only warp 15 active) to capture the (512,512) cell;
// SigR computed post-loop from 4 Sig loads.

#define NN     512
#define BB     32
#define KS     8
#define WPS    16
#define RINGSZ 32
#define PMAIN  142   // main periods 0..141; epilogue = period 142

__global__ __launch_bounds__(512, 1)
void softdtw_k7(const float* __restrict__ D, const float* __restrict__ Sig,
                float* __restrict__ out) {
    __shared__ float2 ring[WPS][RINGSZ];

    const int b    = blockIdx.x;
    const int t    = threadIdx.x;
    const int lane = t & 31;
    const int w    = t >> 5;
    const int r    = t + 1;            // matrix row, 1-indexed
    const int rb   = 32 * w;           // boundary row feeding this warp

    ((float2*)ring)[t] = make_float2(0.f, 0.f);   // 16*32 = 512 entries

    const size_t base = (size_t)b * NN * NN;
    const float* rowD = D + base + (size_t)t * NN;
    const bool pub = (lane == 31) && (w < WPS - 1);

    // own-row state at diag d-1, and carried neighbor-row values at d-1
    float E1 = 0.f, D1 = 0.f;
    float cpE = (t == 0) ? 1.f : 0.f;  // sentinel: E(R[0][0]=0) = 1 enters at d=2
    float cpD = 0.f;

    // col of D value for substep s of period p: 8p + coff + s
    const int coff = -40 * w - lane;
    float dc[KS], dn[KS];
#pragma unroll
    for (int s = 0; s < KS; ++s) {
        int c = coff + s;
        dc[s] = ((unsigned)c < NN) ? rowD[c] : 0.f;
    }
    __syncthreads();

    const int wlo = 32 * w + 2;        // first diag any row of this warp is active
    const int whi = 32 * w + 544;      // last diag (row 32w+32 at col 512)

#pragma unroll 2
    for (int p = 0; p < PMAIN; ++p) {
        const int dbase = 2 + KS * (p - w);

        // prefetch next period's D values
#pragma unroll
        for (int s = 0; s < KS; ++s) {
            int c = 8 * (p + 1) + coff + s;
            dn[s] = ((unsigned)c < NN) ? rowD[c] : 0.f;
        }

        if (dbase + KS - 1 >= wlo && dbase <= whi) {   // warp-uniform
#pragma unroll
            for (int s = 0; s < KS; ++s) {
                const int d = dbase + s;
                // neighbor-row (r-1) values at diag d-1
                float sE = __shfl_up_sync(0xffffffffu, E1, 1);
                float sD = __shfl_up_sync(0xffffffffu, D1, 1);
                float2 rv = ring[w][(d - 1) & (RINGSZ - 1)];   // broadcast LDS
                bool bvalid = ((unsigned)(d - 2 - rb) < NN);   // 1 <= (d-1)-rb <= 512
                float pE1 = (lane == 0) ? (bvalid ? rv.x : 0.f) : sE;
                float pD1 = (lane == 0) ? (bvalid ? rv.y : 0.f) : sD;

                // cell (r, d-r): weights {cpE, pE1, E1} over D preds {cpD, pD1, D1}
                float sum = (cpE + pE1) + E1;
                float iv  = __fdividef(1.f, sum);
                float num = fmaf(E1, D1, fmaf(pE1, pD1, cpE * cpD));
                float nR  = fmaf(num, iv, dc[s]);
                bool v = ((unsigned)(d - r - 1) < NN);
                float En = v ? __expf(-nR) : 0.f;

                cpE = pE1; cpD = pD1;
                E1 = En;  D1 = dc[s];
                if (pub) ring[w + 1][d & (RINGSZ - 1)] = make_float2(E1, D1);
            }
        }

#pragma unroll
        for (int s = 0; s < KS; ++s) dc[s] = dn[s];
        __syncthreads();
    }

    // ---- peeled final period (only warp 15 active): capture cell (512,512) ----
    float capE2 = 0.f, capE1 = 0.f, capE0 = 0.f, capR = 0.f;
    {
        const int dbase = 2 + KS * (PMAIN - w);
        if (dbase + KS - 1 >= wlo && dbase <= whi) {
#pragma unroll
            for (int s = 0; s < KS; ++s) {
                const int d = dbase + s;
                float sE = __shfl_up_sync(0xffffffffu, E1, 1);
                float sD = __shfl_up_sync(0xffffffffu, D1, 1);
                float2 rv = ring[w][(d - 1) & (RINGSZ - 1)];
                bool bvalid = ((unsigned)(d - 2 - rb) < NN);
                float pE1 = (lane == 0) ? (bvalid ? rv.x : 0.f) : sE;
                float pD1 = (lane == 0) ? (bvalid ? rv.y : 0.f) : sD;
                float sum = (cpE + pE1) + E1;
                float iv  = __fdividef(1.f, sum);
                float num = fmaf(E1, D1, fmaf(pE1, pD1, cpE * cpD));
                float nR  = fmaf(num, iv, dc[s]);
                bool v = ((unsigned)(d - r - 1) < NN);
                if (v) { capE2 = cpE; capE1 = pE1; capE0 = E1; capR = nR; }
                float En = v ? __expf(-nR) : 0.f;
                cpE = pE1; cpD = pD1;
                E1 = En;  D1 = dc[s];
            }
        }
    }

    if (t == NN - 1) {   // t = 511: row 512; its last valid diag is 1024
        // final cell (512,512): weights {capE2, capE1, capE0} over
        // Sig preds (511,511), (511,512), (512,511); base Sig(512,512).
        const float* Sg = Sig + base;
        float s00 = Sg[510 * NN + 510];
        float s01 = Sg[510 * NN + 511];
        float s10 = Sg[511 * NN + 510];
        float s11 = Sg[511 * NN + 511];
        float sum = (capE2 + capE1) + capE0;
        float lastS = s11 + fmaf(capE2, s00, fmaf(capE1, s01, capE0 * s10)) / sum;
        out[b]      = capR;    // R[b, N, M]
        out[BB + b] = lastS;   // SigR[b, N, M]
    }
}

extern "C" void kernel_launch(void* const* d_in, const int* in_sizes, int n_in,
                              void* d_out, int out_size) {
    const float* D   = (const float*)d_in[0];
    const float* Sig = (const float*)d_in[1];
    float* out = (float*)d_out;
    softdtw_k7<<<BB, 512>>>(D, Sig, out);
}